// round 9
// baseline (speedup 1.0000x reference)
#include <cuda_runtime.h>
#include <cuda_fp16.h>
#include <cstdint>
#include <math.h>

#define BB 4
#define SS 2048
#define DD 1024

// Scratch (__device__ globals — allocation-free rule). 16B-aligned for cp.async.
__device__ __align__(256) __half g_qh [(size_t)BB * SS * DD];
__device__ __align__(256) __half g_kh [(size_t)BB * SS * DD];
__device__ __align__(256) __half g_vh [(size_t)BB * SS * DD];
__device__ __align__(256) __half g_WqT[(size_t)DD * DD];
__device__ __align__(256) __half g_WkT[(size_t)DD * DD];
__device__ __align__(256) __half g_WvT[(size_t)DD * DD];
__device__ __align__(256) __half g_Qp [(size_t)BB * SS * DD];
__device__ __align__(256) __half g_Kp [(size_t)BB * SS * DD];
__device__ __align__(256) __half g_Vp [(size_t)BB * SS * DD];
__device__ __align__(256) __half g_VpT[(size_t)BB * SS * DD];
__device__ __align__(256) float  g_Sc [(size_t)BB * SS * SS];
__device__ __align__(256) __half g_Ph [(size_t)BB * SS * SS];

// ---------------------------------------------------------------------------
// PTX helpers
// ---------------------------------------------------------------------------
__device__ __forceinline__ void cp16(uint32_t dst, const void* src) {
    asm volatile("cp.async.cg.shared.global [%0], [%1], 16;" :: "r"(dst), "l"(src));
}
__device__ __forceinline__ void cp_commit() {
    asm volatile("cp.async.commit_group;");
}
__device__ __forceinline__ void ldsm4(uint32_t* r, uint32_t addr) {
    asm volatile("ldmatrix.sync.aligned.m8n8.x4.shared.b16 {%0,%1,%2,%3}, [%4];"
        : "=r"(r[0]), "=r"(r[1]), "=r"(r[2]), "=r"(r[3]) : "r"(addr));
}
__device__ __forceinline__ void mma_f16(float* c, const uint32_t* a, const uint32_t* b) {
    asm volatile(
        "mma.sync.aligned.m16n8k16.row.col.f32.f16.f16.f32 "
        "{%0,%1,%2,%3}, {%4,%5,%6,%7}, {%8,%9}, {%0,%1,%2,%3};"
        : "+f"(c[0]), "+f"(c[1]), "+f"(c[2]), "+f"(c[3])
        : "r"(a[0]), "r"(a[1]), "r"(a[2]), "r"(a[3]), "r"(b[0]), "r"(b[1]));
}

// ---------------------------------------------------------------------------
// FP16 TN tensor-core GEMM: C[m,n] = alpha * sum_k A[m,k]*B[n,k] (+ bias[n])
//   A: [M,K] half row-major, B: [N,K] half row-major (both K-major).
//   256 threads, CTA tile 128x128x64, 8 warps (2m x 4n, warp tile 64x32),
//   3-stage cp.async pipeline; A-fragments double-buffered, B just-in-time.
//   ~120 regs/thread -> 2 CTA/SM = 16 warps/SM (latency hiding).
// ---------------------------------------------------------------------------
#define STAGES 3
#define BK 64
#define AST 72                              // smem row stride in halves (144 B)
#define TILE_HALVES (128 * AST)             // 9216
#define STAGE_BYTES (2 * TILE_HALVES * 2)   // 36864
#define GEMM_SMEM (STAGES * STAGE_BYTES)    // 110592

template <bool HAS_BIAS, bool OUT_HALF>
__global__ __launch_bounds__(256, 2)
void hgemm_tn(const __half* __restrict__ A, const __half* __restrict__ B,
              const float* __restrict__ bias, void* __restrict__ Cv,
              int N, int K, float alpha, long sAz, long sBz, long sCz)
{
    extern __shared__ __half sm[];
    const int tid  = threadIdx.x;
    const int lane = tid & 31;
    const int warp = tid >> 5;
    const int m0 = blockIdx.y * 128;
    const int n0 = blockIdx.x * 128;

    const __half* Ab = A + (long)blockIdx.z * sAz;
    const __half* Bb = B + (long)blockIdx.z * sBz;

    // 8 warps: 2(m) x 4(n); warp tile 64x32
    const int wm = (warp >> 2) * 64;
    const int wn = (warp & 3) * 32;
    const int r  = lane >> 2;
    const int cc = lane & 3;

    const uint32_t smBase = (uint32_t)__cvta_generic_to_shared(sm);

    // ldmatrix per-lane offsets (in halves)
    const int aLane = (lane & 15) * AST + (lane >> 4) * 8;
    const int bLane = (((lane >> 4) << 3) + (lane & 7)) * AST + ((lane >> 3) & 1) * 8;

    auto load_tiles = [&](int stage, int k0) {
        const uint32_t aS = smBase + (uint32_t)stage * STAGE_BYTES;
        const uint32_t bS = aS + TILE_HALVES * 2;
#pragma unroll
        for (int i = 0; i < 4; i++) {
            const int c   = tid + 256 * i;     // 1024 chunks of 8 halves per tile
            const int row = c >> 3;
            const int c16 = (c & 7) * 8;
            cp16(aS + (uint32_t)(row * AST + c16) * 2, Ab + (long)(m0 + row) * K + k0 + c16);
            cp16(bS + (uint32_t)(row * AST + c16) * 2, Bb + (long)(n0 + row) * K + k0 + c16);
        }
    };

    float acc[4][4][4];
#pragma unroll
    for (int mt = 0; mt < 4; mt++)
#pragma unroll
        for (int nt = 0; nt < 4; nt++)
#pragma unroll
            for (int i = 0; i < 4; i++) acc[mt][nt][i] = 0.0f;

    const int KT = K / BK;
#pragma unroll
    for (int s = 0; s < STAGES; s++) {
        if (s < KT) { load_tiles(s, s * BK); cp_commit(); }
    }

    uint32_t afr[2][4][4];   // A fragments, double-buffered across k16 steps
    uint32_t bfr[2][4];      // B fragments, just-in-time per k16 step

    for (int t = 0; t < KT; t++) {
        const int rem = KT - 1 - t;
        if (rem >= 2)      asm volatile("cp.async.wait_group 2;");
        else if (rem == 1) asm volatile("cp.async.wait_group 1;");
        else               asm volatile("cp.async.wait_group 0;");
        __syncthreads();

        const int stage = t % STAGES;
        const uint32_t aS = smBase + (uint32_t)stage * STAGE_BYTES;
        const uint32_t bS = aS + TILE_HALVES * 2;

        // prefetch A fragments for k16 step 0
#pragma unroll
        for (int mt = 0; mt < 4; mt++)
            ldsm4(afr[0][mt], aS + (uint32_t)((wm + mt * 16) * AST + aLane) * 2);

#pragma unroll
        for (int ks = 0; ks < BK / 16; ks++) {
            const int cur = ks & 1;
            const int nxt = cur ^ 1;
            const int k16 = ks * 16;
            // B fragments for current step (issue first so latency overlaps A-prefetch)
#pragma unroll
            for (int ng = 0; ng < 2; ng++)
                ldsm4(&bfr[ng][0] - 0 + 0 == nullptr ? &bfr[ng][0] : &bfr[ng][0],  // (no-op guard)
                      bS + (uint32_t)((wn + ng * 16) * AST + k16 + bLane) * 2);
            // A fragments for next step
            if (ks < BK / 16 - 1) {
                const int k16n = (ks + 1) * 16;
#pragma unroll
                for (int mt = 0; mt < 4; mt++)
                    ldsm4(afr[nxt][mt], aS + (uint32_t)((wm + mt * 16) * AST + k16n + aLane) * 2);
            }
#pragma unroll
            for (int mt = 0; mt < 4; mt++)
#pragma unroll
                for (int nt = 0; nt < 4; nt++)
                    mma_f16(acc[mt][nt], afr[cur][mt], &bfr[nt >> 1][(nt & 1) * 2]);
        }
        __syncthreads();

        if (t + STAGES < KT) { load_tiles(stage, (t + STAGES) * BK); cp_commit(); }
    }

    // epilogue
#pragma unroll
    for (int mt = 0; mt < 4; mt++) {
        const long row0 = m0 + wm + mt * 16 + r;
#pragma unroll
        for (int nt = 0; nt < 4; nt++) {
            const int colb = n0 + wn + nt * 8 + 2 * cc;
            float x0 = acc[mt][nt][0] * alpha;
            float x1 = acc[mt][nt][1] * alpha;
            float x2 = acc[mt][nt][2] * alpha;
            float x3 = acc[mt][nt][3] * alpha;
            if (HAS_BIAS) {
                const float b0 = bias[colb], b1 = bias[colb + 1];
                x0 += b0; x1 += b1; x2 += b0; x3 += b1;
            }
            if (OUT_HALF) {
                __half* Cb = (__half*)Cv + (long)blockIdx.z * sCz;
                *(__half2*)(Cb + row0 * N + colb)       = __floats2half2_rn(x0, x1);
                *(__half2*)(Cb + (row0 + 8) * N + colb) = __floats2half2_rn(x2, x3);
            } else {
                float* Cb = (float*)Cv + (long)blockIdx.z * sCz;
                *(float2*)(Cb + row0 * N + colb)       = make_float2(x0, x1);
                *(float2*)(Cb + (row0 + 8) * N + colb) = make_float2(x2, x3);
            }
        }
    }
}

// ---------------------------------------------------------------------------
// Batched fp32 -> fp16(rn): z selects which of 3 arrays
// ---------------------------------------------------------------------------
__global__ __launch_bounds__(256)
void f2h3_kernel(const float* __restrict__ a0, const float* __restrict__ a1,
                 const float* __restrict__ a2, __half* __restrict__ o0,
                 __half* __restrict__ o1, __half* __restrict__ o2, long n4)
{
    const float* in = (blockIdx.z == 0) ? a0 : (blockIdx.z == 1) ? a1 : a2;
    __half* out     = (blockIdx.z == 0) ? o0 : (blockIdx.z == 1) ? o1 : o2;
    long i = (long)blockIdx.x * blockDim.x + threadIdx.x;
    const long stride = (long)gridDim.x * blockDim.x;
    for (; i < n4; i += stride) {
        float4 v = ((const float4*)in)[i];
        __half2* o = (__half2*)(out + i * 4);
        o[0] = __floats2half2_rn(v.x, v.y);
        o[1] = __floats2half2_rn(v.z, v.w);
    }
}

// ---------------------------------------------------------------------------
// Batched transpose + convert: W f32 [K][N] -> half [N][K] (z selects weight)
// ---------------------------------------------------------------------------
__global__ __launch_bounds__(256)
void wtrans3_kernel(const float* __restrict__ a0, const float* __restrict__ a1,
                    const float* __restrict__ a2, __half* __restrict__ o0,
                    __half* __restrict__ o1, __half* __restrict__ o2)
{
    const float* in = (blockIdx.z == 0) ? a0 : (blockIdx.z == 1) ? a1 : a2;
    __half* out     = (blockIdx.z == 0) ? o0 : (blockIdx.z == 1) ? o1 : o2;
    __shared__ float t[32][33];
    const int bx = blockIdx.x * 32;   // n
    const int by = blockIdx.y * 32;   // k
    const int tx = threadIdx.x, ty = threadIdx.y;
#pragma unroll
    for (int i = ty; i < 32; i += 8)
        t[i][tx] = in[(long)(by + i) * DD + bx + tx];
    __syncthreads();
#pragma unroll
    for (int i = ty; i < 32; i += 8)
        out[(long)(bx + i) * DD + by + tx] = __float2half_rn(t[tx][i]);
}

// ---------------------------------------------------------------------------
// Half transpose (batched): in [rows][cols] -> out [cols][rows]
// ---------------------------------------------------------------------------
__global__ __launch_bounds__(256)
void htrans_kernel(const __half* __restrict__ in, __half* __restrict__ out,
                   int rows, int cols)
{
    __shared__ __half t[32][34];
    const int bx = blockIdx.x * 32;   // col
    const int by = blockIdx.y * 32;   // row
    const int tx = threadIdx.x, ty = threadIdx.y;
    const __half* ib = in  + (long)blockIdx.z * rows * cols;
    __half*       ob = out + (long)blockIdx.z * rows * cols;
#pragma unroll
    for (int i = ty; i < 32; i += 8)
        t[i][tx] = ib[(long)(by + i) * cols + bx + tx];
    __syncthreads();
#pragma unroll
    for (int i = ty; i < 32; i += 8)
        ob[(long)(bx + i) * rows + by + tx] = t[tx][i];
}

// ---------------------------------------------------------------------------
// Row softmax over 2048 fp32 cols -> fp16 probabilities
// ---------------------------------------------------------------------------
__global__ __launch_bounds__(256)
void softmax2048_h(const float* __restrict__ S, __half* __restrict__ P)
{
    const float* row = S + (long)blockIdx.x * SS;
    __half*      po  = P + (long)blockIdx.x * SS;
    const int t = threadIdx.x;

    float v[8];
    float mx = -1e30f;
#pragma unroll
    for (int i = 0; i < 8; i++) {
        v[i] = row[t + i * 256];
        mx = fmaxf(mx, v[i]);
    }
#pragma unroll
    for (int o = 16; o > 0; o >>= 1)
        mx = fmaxf(mx, __shfl_xor_sync(0xFFFFFFFFu, mx, o));

    __shared__ float red[8];
    if ((t & 31) == 0) red[t >> 5] = mx;
    __syncthreads();
    float bmax = red[0];
#pragma unroll
    for (int i = 1; i < 8; i++) bmax = fmaxf(bmax, red[i]);
    __syncthreads();

    float sum = 0.0f;
#pragma unroll
    for (int i = 0; i < 8; i++) {
        v[i] = __expf(v[i] - bmax);
        sum += v[i];
    }
#pragma unroll
    for (int o = 16; o > 0; o >>= 1)
        sum += __shfl_xor_sync(0xFFFFFFFFu, sum, o);
    if ((t & 31) == 0) red[t >> 5] = sum;
    __syncthreads();
    float tot = 0.0f;
#pragma unroll
    for (int i = 0; i < 8; i++) tot += red[i];

    const float inv = __frcp_rn(tot);
#pragma unroll
    for (int i = 0; i < 8; i++)
        po[t + i * 256] = __float2half_rn(v[i] * inv);
}

// ---------------------------------------------------------------------------
extern "C" void kernel_launch(void* const* d_in, const int* in_sizes, int n_in,
                              void* d_out, int out_size)
{
    const float* q  = (const float*)d_in[0];
    const float* k  = (const float*)d_in[1];
    const float* v  = (const float*)d_in[2];
    const float* Wq = (const float*)d_in[3];
    const float* bq = (const float*)d_in[4];
    const float* Wk = (const float*)d_in[5];
    const float* bk = (const float*)d_in[6];
    const float* Wv = (const float*)d_in[7];
    const float* bv = (const float*)d_in[8];
    float* out = (float*)d_out;

    __half *qh, *kh, *vh, *WqT, *WkT, *WvT, *Qp, *Kp, *Vp, *VpT, *Ph;
    float *Sc;
    cudaGetSymbolAddress((void**)&qh,  g_qh);
    cudaGetSymbolAddress((void**)&kh,  g_kh);
    cudaGetSymbolAddress((void**)&vh,  g_vh);
    cudaGetSymbolAddress((void**)&WqT, g_WqT);
    cudaGetSymbolAddress((void**)&WkT, g_WkT);
    cudaGetSymbolAddress((void**)&WvT, g_WvT);
    cudaGetSymbolAddress((void**)&Qp,  g_Qp);
    cudaGetSymbolAddress((void**)&Kp,  g_Kp);
    cudaGetSymbolAddress((void**)&Vp,  g_Vp);
    cudaGetSymbolAddress((void**)&VpT, g_VpT);
    cudaGetSymbolAddress((void**)&Sc,  g_Sc);
    cudaGetSymbolAddress((void**)&Ph,  g_Ph);

    cudaFuncSetAttribute(hgemm_tn<true,  true >, cudaFuncAttributeMaxDynamicSharedMemorySize, GEMM_SMEM);
    cudaFuncSetAttribute(hgemm_tn<false, false>, cudaFuncAttributeMaxDynamicSharedMemorySize, GEMM_SMEM);

    const long nQKV = (long)BB * SS * DD;

    // 1: convert q/k/v to fp16 (one launch, grid.z = 3)
    {
        dim3 g(1024, 1, 3);
        f2h3_kernel<<<g, 256>>>(q, k, v, qh, kh, vh, nQKV / 4);
    }
    // 2: transpose+convert weights (one launch, grid.z = 3)
    {
        dim3 g(32, 32, 3), b(32, 8);
        wtrans3_kernel<<<g, b>>>(Wq, Wk, Wv, WqT, WkT, WvT);
    }

    const dim3 blk(256);

    // 3-5: Projections (TN, bias, half out): M=8192, N=1024, K=1024
    {
        dim3 g(DD / 128, (BB * SS) / 128, 1);
        hgemm_tn<true, true><<<g, blk, GEMM_SMEM>>>(qh, WqT, bq, Qp, DD, DD, 1.0f, 0, 0, 0);
        hgemm_tn<true, true><<<g, blk, GEMM_SMEM>>>(kh, WkT, bk, Kp, DD, DD, 1.0f, 0, 0, 0);
        hgemm_tn<true, true><<<g, blk, GEMM_SMEM>>>(vh, WvT, bv, Vp, DD, DD, 1.0f, 0, 0, 0);
    }

    // 6: Scores (TN, f32 out): per batch M=N=2048, K=1024, alpha=1/32
    {
        dim3 g(SS / 128, SS / 128, BB);
        hgemm_tn<false, false><<<g, blk, GEMM_SMEM>>>(Qp, Kp, nullptr, Sc,
                                                      SS, DD, 0.03125f,
                                                      (long)SS * DD, (long)SS * DD, (long)SS * SS);
    }

    // 7: Softmax (f32 -> f16 probs)
    softmax2048_h<<<BB * SS, 256>>>(Sc, Ph);

    // 8: transpose Vp per batch: [S][D] -> [D][S]  (needed only by PV)
    {
        dim3 g(DD / 32, SS / 32, BB), b(32, 8);
        htrans_kernel<<<g, b>>>(Vp, VpT, SS, DD);
    }

    // 9: PV (TN, f32 out): A=Ph [S,S], B=VpT [D][S]; M=2048, N=1024, K=2048
    {
        dim3 g(DD / 128, SS / 128, BB);
        hgemm_tn<false, false><<<g, blk, GEMM_SMEM>>>(Ph, VpT, nullptr, out,
                                                      DD, SS, 1.0f,
                                                      (long)SS * SS, (long)SS * DD, (long)SS * DD);
    }
}

// round 10
// speedup vs baseline: 1.2148x; 1.2148x over previous
#include <cuda_runtime.h>
#include <cuda_fp16.h>
#include <cstdint>
#include <math.h>

#define BB 4
#define SS 2048
#define DD 1024

// Scratch (__device__ globals — allocation-free rule). 16B-aligned for cp.async.
__device__ __align__(256) __half g_qh [(size_t)BB * SS * DD];
__device__ __align__(256) __half g_kh [(size_t)BB * SS * DD];
__device__ __align__(256) __half g_vh [(size_t)BB * SS * DD];
__device__ __align__(256) __half g_WqT[(size_t)DD * DD];
__device__ __align__(256) __half g_WkT[(size_t)DD * DD];
__device__ __align__(256) __half g_WvT[(size_t)DD * DD];
__device__ __align__(256) __half g_Qp [(size_t)BB * SS * DD];
__device__ __align__(256) __half g_Kp [(size_t)BB * SS * DD];
__device__ __align__(256) __half g_Vp [(size_t)BB * SS * DD];
__device__ __align__(256) __half g_VpT[(size_t)BB * SS * DD];
__device__ __align__(256) float  g_Sc [(size_t)BB * SS * SS];
__device__ __align__(256) __half g_Ph [(size_t)BB * SS * SS];

// ---------------------------------------------------------------------------
// PTX helpers
// ---------------------------------------------------------------------------
__device__ __forceinline__ void cp16(uint32_t dst, const void* src) {
    asm volatile("cp.async.cg.shared.global [%0], [%1], 16;" :: "r"(dst), "l"(src));
}
__device__ __forceinline__ void cp_commit() {
    asm volatile("cp.async.commit_group;");
}
__device__ __forceinline__ void ldsm4(uint32_t* r, uint32_t addr) {
    asm volatile("ldmatrix.sync.aligned.m8n8.x4.shared.b16 {%0,%1,%2,%3}, [%4];"
        : "=r"(r[0]), "=r"(r[1]), "=r"(r[2]), "=r"(r[3]) : "r"(addr));
}
__device__ __forceinline__ void mma_f16(float* c, const uint32_t* a, const uint32_t* b) {
    asm volatile(
        "mma.sync.aligned.m16n8k16.row.col.f32.f16.f16.f32 "
        "{%0,%1,%2,%3}, {%4,%5,%6,%7}, {%8,%9}, {%0,%1,%2,%3};"
        : "+f"(c[0]), "+f"(c[1]), "+f"(c[2]), "+f"(c[3])
        : "r"(a[0]), "r"(a[1]), "r"(a[2]), "r"(a[3]), "r"(b[0]), "r"(b[1]));
}

// SW128 swizzle: tile row = 128 B (64 halves), 8 x 16B chunks per row.
// byte addr = row*128 + chunk*16  ->  chunk' = chunk ^ (row & 7)
__device__ __forceinline__ uint32_t swz(uint32_t base, int row, int chunk) {
    return base + (uint32_t)(row * 128) + (uint32_t)((chunk ^ (row & 7)) << 4);
}

// ---------------------------------------------------------------------------
// FP16 TN tensor-core GEMM: C[m,n] = alpha * sum_k A[m,k]*B[n,k] (+ bias[n])
//   A: [M,K] half row-major, B: [N,K] half row-major (both K-major).
//   128 threads, CTA tile 128x128x64, 4 warps (2m x 2n, warp tile 64x64),
//   3-stage cp.async pipeline (single syncthreads per stage),
//   SW128-swizzled smem (conflict-free ldsm), fragment double-buffering.
// ---------------------------------------------------------------------------
#define STAGES 3
#define BK 64
#define TILE_BYTES 16384                    // 128 rows x 128 B
#define STAGE_BYTES (2 * TILE_BYTES)        // 32768
#define GEMM_SMEM (STAGES * STAGE_BYTES)    // 98304

template <bool HAS_BIAS, bool OUT_HALF>
__global__ __launch_bounds__(128, 2)
void hgemm_tn(const __half* __restrict__ A, const __half* __restrict__ B,
              const float* __restrict__ bias, void* __restrict__ Cv,
              int N, int K, float alpha, long sAz, long sBz, long sCz)
{
    extern __shared__ __align__(1024) char smraw[];
    const int tid  = threadIdx.x;
    const int lane = tid & 31;
    const int warp = tid >> 5;
    const int m0 = blockIdx.y * 128;
    const int n0 = blockIdx.x * 128;

    const __half* Ab = A + (long)blockIdx.z * sAz;
    const __half* Bb = B + (long)blockIdx.z * sBz;

    // 4 warps: 2(m) x 2(n); warp tile 64x64
    const int wm = (warp >> 1) * 64;
    const int wn = (warp & 1) * 64;
    const int r  = lane >> 2;
    const int cc = lane & 3;

    const uint32_t smBase = (uint32_t)__cvta_generic_to_shared(smraw);

    // ldmatrix lane mapping (row-within-16, 16B sub-chunk select)
    const int aRow = lane & 15;            // A: rows 0..15 of the 16-row group
    const int aSub = lane >> 4;            // 0/1 -> +0/+8 halves
    const int bRow = ((lane >> 4) << 3) + (lane & 7);   // B: n-row within group
    const int bSub = (lane >> 3) & 1;

    auto load_tiles = [&](int stage, int k0) {
        const uint32_t aS = smBase + (uint32_t)stage * STAGE_BYTES;
        const uint32_t bS = aS + TILE_BYTES;
#pragma unroll
        for (int i = 0; i < 8; i++) {
            const int c     = tid + 128 * i;      // 1024 chunks per tile
            const int row   = c >> 3;
            const int chunk = c & 7;
            cp16(swz(aS, row, chunk), Ab + (long)(m0 + row) * K + k0 + chunk * 8);
            cp16(swz(bS, row, chunk), Bb + (long)(n0 + row) * K + k0 + chunk * 8);
        }
    };

    float acc[4][8][4];
#pragma unroll
    for (int mt = 0; mt < 4; mt++)
#pragma unroll
        for (int nt = 0; nt < 8; nt++)
#pragma unroll
            for (int i = 0; i < 4; i++) acc[mt][nt][i] = 0.0f;

    const int KT = K / BK;
    load_tiles(0, 0);      cp_commit();
    if (KT > 1) { load_tiles(1, BK); cp_commit(); }

    uint32_t afr[2][4][4], bfr[2][4][4];

    for (int t = 0; t < KT; t++) {
        if (t + 2 < KT) asm volatile("cp.async.wait_group 1;");
        else            asm volatile("cp.async.wait_group 0;");
        __syncthreads();
        // issue next stage load AFTER the barrier: all warps have finished
        // reading the buffer being overwritten (consumed at iteration t-1).
        if (t + 2 < KT) { load_tiles((t + 2) % STAGES, (t + 2) * BK); cp_commit(); }

        const int stage = t % STAGES;
        const uint32_t aS = smBase + (uint32_t)stage * STAGE_BYTES;
        const uint32_t bS = aS + TILE_BYTES;

        // prefetch fragments for k16 step 0  (chunk = k16/8 + sub)
#pragma unroll
        for (int mt = 0; mt < 4; mt++)
            ldsm4(afr[0][mt], swz(aS, wm + mt * 16 + aRow, aSub));
#pragma unroll
        for (int ng = 0; ng < 4; ng++)
            ldsm4(bfr[0][ng], swz(bS, wn + ng * 16 + bRow, bSub));

#pragma unroll
        for (int ks = 0; ks < BK / 16; ks++) {
            const int cur = ks & 1;
            const int nxt = cur ^ 1;
            if (ks < BK / 16 - 1) {
                const int ch = (ks + 1) * 2;   // k16 -> chunk offset (16 halves = 2 chunks)
#pragma unroll
                for (int mt = 0; mt < 4; mt++)
                    ldsm4(afr[nxt][mt], swz(aS, wm + mt * 16 + aRow, ch + aSub));
#pragma unroll
                for (int ng = 0; ng < 4; ng++)
                    ldsm4(bfr[nxt][ng], swz(bS, wn + ng * 16 + bRow, ch + bSub));
            }
#pragma unroll
            for (int mt = 0; mt < 4; mt++)
#pragma unroll
                for (int nt = 0; nt < 8; nt++)
                    mma_f16(acc[mt][nt], afr[cur][mt], &bfr[cur][nt >> 1][(nt & 1) * 2]);
        }
    }

    // epilogue
#pragma unroll
    for (int mt = 0; mt < 4; mt++) {
        const long row0 = m0 + wm + mt * 16 + r;
#pragma unroll
        for (int nt = 0; nt < 8; nt++) {
            const int colb = n0 + wn + nt * 8 + 2 * cc;
            float x0 = acc[mt][nt][0] * alpha;
            float x1 = acc[mt][nt][1] * alpha;
            float x2 = acc[mt][nt][2] * alpha;
            float x3 = acc[mt][nt][3] * alpha;
            if (HAS_BIAS) {
                const float b0 = bias[colb], b1 = bias[colb + 1];
                x0 += b0; x1 += b1; x2 += b0; x3 += b1;
            }
            if (OUT_HALF) {
                __half* Cb = (__half*)Cv + (long)blockIdx.z * sCz;
                *(__half2*)(Cb + row0 * N + colb)       = __floats2half2_rn(x0, x1);
                *(__half2*)(Cb + (row0 + 8) * N + colb) = __floats2half2_rn(x2, x3);
            } else {
                float* Cb = (float*)Cv + (long)blockIdx.z * sCz;
                *(float2*)(Cb + row0 * N + colb)       = make_float2(x0, x1);
                *(float2*)(Cb + (row0 + 8) * N + colb) = make_float2(x2, x3);
            }
        }
    }
}

// ---------------------------------------------------------------------------
// Batched fp32 -> fp16(rn): z selects which of 3 arrays
// ---------------------------------------------------------------------------
__global__ __launch_bounds__(256)
void f2h3_kernel(const float* __restrict__ a0, const float* __restrict__ a1,
                 const float* __restrict__ a2, __half* __restrict__ o0,
                 __half* __restrict__ o1, __half* __restrict__ o2, long n4)
{
    const float* in = (blockIdx.z == 0) ? a0 : (blockIdx.z == 1) ? a1 : a2;
    __half* out     = (blockIdx.z == 0) ? o0 : (blockIdx.z == 1) ? o1 : o2;
    long i = (long)blockIdx.x * blockDim.x + threadIdx.x;
    const long stride = (long)gridDim.x * blockDim.x;
    for (; i < n4; i += stride) {
        float4 v = ((const float4*)in)[i];
        __half2* o = (__half2*)(out + i * 4);
        o[0] = __floats2half2_rn(v.x, v.y);
        o[1] = __floats2half2_rn(v.z, v.w);
    }
}

// ---------------------------------------------------------------------------
// Batched transpose + convert: W f32 [K][N] -> half [N][K] (z selects weight)
// ---------------------------------------------------------------------------
__global__ __launch_bounds__(256)
void wtrans3_kernel(const float* __restrict__ a0, const float* __restrict__ a1,
                    const float* __restrict__ a2, __half* __restrict__ o0,
                    __half* __restrict__ o1, __half* __restrict__ o2)
{
    const float* in = (blockIdx.z == 0) ? a0 : (blockIdx.z == 1) ? a1 : a2;
    __half* out     = (blockIdx.z == 0) ? o0 : (blockIdx.z == 1) ? o1 : o2;
    __shared__ float t[32][33];
    const int bx = blockIdx.x * 32;   // n
    const int by = blockIdx.y * 32;   // k
    const int tx = threadIdx.x, ty = threadIdx.y;
#pragma unroll
    for (int i = ty; i < 32; i += 8)
        t[i][tx] = in[(long)(by + i) * DD + bx + tx];
    __syncthreads();
#pragma unroll
    for (int i = ty; i < 32; i += 8)
        out[(long)(bx + i) * DD + by + tx] = __float2half_rn(t[tx][i]);
}

// ---------------------------------------------------------------------------
// Half transpose (batched): in [rows][cols] -> out [cols][rows]
// ---------------------------------------------------------------------------
__global__ __launch_bounds__(256)
void htrans_kernel(const __half* __restrict__ in, __half* __restrict__ out,
                   int rows, int cols)
{
    __shared__ __half t[32][34];
    const int bx = blockIdx.x * 32;   // col
    const int by = blockIdx.y * 32;   // row
    const int tx = threadIdx.x, ty = threadIdx.y;
    const __half* ib = in  + (long)blockIdx.z * rows * cols;
    __half*       ob = out + (long)blockIdx.z * rows * cols;
#pragma unroll
    for (int i = ty; i < 32; i += 8)
        t[i][tx] = ib[(long)(by + i) * cols + bx + tx];
    __syncthreads();
#pragma unroll
    for (int i = ty; i < 32; i += 8)
        ob[(long)(bx + i) * rows + by + tx] = t[tx][i];
}

// ---------------------------------------------------------------------------
// Row softmax over 2048 fp32 cols -> fp16 probabilities
// ---------------------------------------------------------------------------
__global__ __launch_bounds__(256)
void softmax2048_h(const float* __restrict__ S, __half* __restrict__ P)
{
    const float* row = S + (long)blockIdx.x * SS;
    __half*      po  = P + (long)blockIdx.x * SS;
    const int t = threadIdx.x;

    float v[8];
    float mx = -1e30f;
#pragma unroll
    for (int i = 0; i < 8; i++) {
        v[i] = row[t + i * 256];
        mx = fmaxf(mx, v[i]);
    }
#pragma unroll
    for (int o = 16; o > 0; o >>= 1)
        mx = fmaxf(mx, __shfl_xor_sync(0xFFFFFFFFu, mx, o));

    __shared__ float red[8];
    if ((t & 31) == 0) red[t >> 5] = mx;
    __syncthreads();
    float bmax = red[0];
#pragma unroll
    for (int i = 1; i < 8; i++) bmax = fmaxf(bmax, red[i]);
    __syncthreads();

    float sum = 0.0f;
#pragma unroll
    for (int i = 0; i < 8; i++) {
        v[i] = __expf(v[i] - bmax);
        sum += v[i];
    }
#pragma unroll
    for (int o = 16; o > 0; o >>= 1)
        sum += __shfl_xor_sync(0xFFFFFFFFu, sum, o);
    if ((t & 31) == 0) red[t >> 5] = sum;
    __syncthreads();
    float tot = 0.0f;
#pragma unroll
    for (int i = 0; i < 8; i++) tot += red[i];

    const float inv = __frcp_rn(tot);
#pragma unroll
    for (int i = 0; i < 8; i++)
        po[t + i * 256] = __float2half_rn(v[i] * inv);
}

// ---------------------------------------------------------------------------
extern "C" void kernel_launch(void* const* d_in, const int* in_sizes, int n_in,
                              void* d_out, int out_size)
{
    const float* q  = (const float*)d_in[0];
    const float* k  = (const float*)d_in[1];
    const float* v  = (const float*)d_in[2];
    const float* Wq = (const float*)d_in[3];
    const float* bq = (const float*)d_in[4];
    const float* Wk = (const float*)d_in[5];
    const float* bk = (const float*)d_in[6];
    const float* Wv = (const float*)d_in[7];
    const float* bv = (const float*)d_in[8];
    float* out = (float*)d_out;

    __half *qh, *kh, *vh, *WqT, *WkT, *WvT, *Qp, *Kp, *Vp, *VpT, *Ph;
    float *Sc;
    cudaGetSymbolAddress((void**)&qh,  g_qh);
    cudaGetSymbolAddress((void**)&kh,  g_kh);
    cudaGetSymbolAddress((void**)&vh,  g_vh);
    cudaGetSymbolAddress((void**)&WqT, g_WqT);
    cudaGetSymbolAddress((void**)&WkT, g_WkT);
    cudaGetSymbolAddress((void**)&WvT, g_WvT);
    cudaGetSymbolAddress((void**)&Qp,  g_Qp);
    cudaGetSymbolAddress((void**)&Kp,  g_Kp);
    cudaGetSymbolAddress((void**)&Vp,  g_Vp);
    cudaGetSymbolAddress((void**)&VpT, g_VpT);
    cudaGetSymbolAddress((void**)&Sc,  g_Sc);
    cudaGetSymbolAddress((void**)&Ph,  g_Ph);

    cudaFuncSetAttribute(hgemm_tn<true,  true >, cudaFuncAttributeMaxDynamicSharedMemorySize, GEMM_SMEM);
    cudaFuncSetAttribute(hgemm_tn<false, false>, cudaFuncAttributeMaxDynamicSharedMemorySize, GEMM_SMEM);

    const long nQKV = (long)BB * SS * DD;

    // 1: convert q/k/v to fp16 (one launch, grid.z = 3)
    {
        dim3 g(1024, 1, 3);
        f2h3_kernel<<<g, 256>>>(q, k, v, qh, kh, vh, nQKV / 4);
    }
    // 2: transpose+convert weights (one launch, grid.z = 3)
    {
        dim3 g(32, 32, 3), b(32, 8);
        wtrans3_kernel<<<g, b>>>(Wq, Wk, Wv, WqT, WkT, WvT);
    }

    const dim3 blk(128);

    // 3-5: Projections (TN, bias, half out): M=8192, N=1024, K=1024
    {
        dim3 g(DD / 128, (BB * SS) / 128, 1);
        hgemm_tn<true, true><<<g, blk, GEMM_SMEM>>>(qh, WqT, bq, Qp, DD, DD, 1.0f, 0, 0, 0);
        hgemm_tn<true, true><<<g, blk, GEMM_SMEM>>>(kh, WkT, bk, Kp, DD, DD, 1.0f, 0, 0, 0);
        hgemm_tn<true, true><<<g, blk, GEMM_SMEM>>>(vh, WvT, bv, Vp, DD, DD, 1.0f, 0, 0, 0);
    }

    // 6: Scores (TN, f32 out): per batch M=N=2048, K=1024, alpha=1/32
    {
        dim3 g(SS / 128, SS / 128, BB);
        hgemm_tn<false, false><<<g, blk, GEMM_SMEM>>>(Qp, Kp, nullptr, Sc,
                                                      SS, DD, 0.03125f,
                                                      (long)SS * DD, (long)SS * DD, (long)SS * SS);
    }

    // 7: Softmax (f32 -> f16 probs)
    softmax2048_h<<<BB * SS, 256>>>(Sc, Ph);

    // 8: transpose Vp per batch: [S][D] -> [D][S]  (needed only by PV)
    {
        dim3 g(DD / 32, SS / 32, BB), b(32, 8);
        htrans_kernel<<<g, b>>>(Vp, VpT, SS, DD);
    }

    // 9: PV (TN, f32 out): A=Ph [S,S], B=VpT [D][S]; M=2048, N=1024, K=2048
    {
        dim3 g(DD / 128, SS / 128, BB);
        hgemm_tn<false, false><<<g, blk, GEMM_SMEM>>>(Ph, VpT, nullptr, out,
                                                      DD, SS, 1.0f,
                                                      (long)SS * SS, (long)SS * DD, (long)SS * DD);
    }
}

// round 11
// speedup vs baseline: 1.2476x; 1.0271x over previous
#include <cuda_runtime.h>
#include <cuda_fp16.h>
#include <cstdint>
#include <math.h>

#define BB 4
#define SS 2048
#define DD 1024

// Scratch (__device__ globals — allocation-free rule). 16B-aligned for cp.async.
__device__ __align__(256) __half g_qh [(size_t)BB * SS * DD];
__device__ __align__(256) __half g_kh [(size_t)BB * SS * DD];
__device__ __align__(256) __half g_vh [(size_t)BB * SS * DD];
__device__ __align__(256) __half g_WqT[(size_t)DD * DD];
__device__ __align__(256) __half g_WkT[(size_t)DD * DD];
__device__ __align__(256) __half g_WvT[(size_t)DD * DD];
__device__ __align__(256) __half g_Qp [(size_t)BB * SS * DD];
__device__ __align__(256) __half g_Kp [(size_t)BB * SS * DD];
__device__ __align__(256) __half g_Vp [(size_t)BB * SS * DD];
__device__ __align__(256) __half g_VpT[(size_t)BB * SS * DD];
__device__ __align__(256) float  g_Sc [(size_t)BB * SS * SS];
__device__ __align__(256) __half g_Ph [(size_t)BB * SS * SS];

// ---------------------------------------------------------------------------
// PTX helpers
// ---------------------------------------------------------------------------
__device__ __forceinline__ void cp16(uint32_t dst, const void* src) {
    asm volatile("cp.async.cg.shared.global [%0], [%1], 16;" :: "r"(dst), "l"(src));
}
__device__ __forceinline__ void cp_commit() {
    asm volatile("cp.async.commit_group;");
}
__device__ __forceinline__ void ldsm4(uint32_t* r, uint32_t addr) {
    asm volatile("ldmatrix.sync.aligned.m8n8.x4.shared.b16 {%0,%1,%2,%3}, [%4];"
        : "=r"(r[0]), "=r"(r[1]), "=r"(r[2]), "=r"(r[3]) : "r"(addr));
}
__device__ __forceinline__ void mma_f16(float* c, const uint32_t* a, const uint32_t* b) {
    asm volatile(
        "mma.sync.aligned.m16n8k16.row.col.f32.f16.f16.f32 "
        "{%0,%1,%2,%3}, {%4,%5,%6,%7}, {%8,%9}, {%0,%1,%2,%3};"
        : "+f"(c[0]), "+f"(c[1]), "+f"(c[2]), "+f"(c[3])
        : "r"(a[0]), "r"(a[1]), "r"(a[2]), "r"(a[3]), "r"(b[0]), "r"(b[1]));
}

// SW128 swizzle: tile row = 128 B (64 halves), 8 x 16B chunks per row.
__device__ __forceinline__ uint32_t swz(uint32_t base, int row, int chunk) {
    return base + (uint32_t)(row * 128) + (uint32_t)((chunk ^ (row & 7)) << 4);
}

// ---------------------------------------------------------------------------
// FP16 TN tensor-core GEMM: C[m,n] = alpha * sum_k A[m,k]*B[n,k] (+ bias[n])
//   128 threads, CTA tile 128x128x64, 4 warps (2m x 2n, warp tile 64x64),
//   3-stage cp.async pipeline (single syncthreads per stage),
//   SW128-swizzled smem, fragment double-buffering.
//   PROJ3: blockIdx.z in {0,1,2} selects (A,B,bias,C) triple (batched projections).
//   Otherwise blockIdx.z = batch index with element strides sAz/sBz/sCz.
// ---------------------------------------------------------------------------
#define STAGES 3
#define BK 64
#define TILE_BYTES 16384                    // 128 rows x 128 B
#define STAGE_BYTES (2 * TILE_BYTES)        // 32768
#define GEMM_SMEM (STAGES * STAGE_BYTES)    // 98304

template <bool PROJ3, bool HAS_BIAS, bool OUT_HALF>
__global__ __launch_bounds__(128, 2)
void hgemm_tn(const __half* __restrict__ A, const __half* __restrict__ B,
              const float* __restrict__ bias, void* __restrict__ Cv,
              int N, int K, float alpha, long sAz, long sBz, long sCz,
              const __half* __restrict__ A1, const __half* __restrict__ B1,
              const float* __restrict__ bias1, void* __restrict__ Cv1,
              const __half* __restrict__ A2, const __half* __restrict__ B2,
              const float* __restrict__ bias2, void* __restrict__ Cv2)
{
    extern __shared__ __align__(1024) char smraw[];
    const int tid  = threadIdx.x;
    const int lane = tid & 31;
    const int warp = tid >> 5;
    const int m0 = blockIdx.y * 128;
    const int n0 = blockIdx.x * 128;
    const int z  = blockIdx.z;

    const __half* Ab;
    const __half* Bb;
    const float*  biasb;
    void*         Cvb;
    if (PROJ3) {
        Ab    = (z == 0) ? A    : (z == 1) ? A1    : A2;
        Bb    = (z == 0) ? B    : (z == 1) ? B1    : B2;
        biasb = (z == 0) ? bias : (z == 1) ? bias1 : bias2;
        Cvb   = (z == 0) ? Cv   : (z == 1) ? Cv1   : Cv2;
    } else {
        Ab    = A + (long)z * sAz;
        Bb    = B + (long)z * sBz;
        biasb = bias;
        Cvb   = Cv;
    }

    // 4 warps: 2(m) x 2(n); warp tile 64x64
    const int wm = (warp >> 1) * 64;
    const int wn = (warp & 1) * 64;
    const int r  = lane >> 2;
    const int cc = lane & 3;

    const uint32_t smBase = (uint32_t)__cvta_generic_to_shared(smraw);

    // ldmatrix lane mapping
    const int aRow = lane & 15;
    const int aSub = lane >> 4;
    const int bRow = ((lane >> 4) << 3) + (lane & 7);
    const int bSub = (lane >> 3) & 1;

    auto load_tiles = [&](int stage, int k0) {
        const uint32_t aS = smBase + (uint32_t)stage * STAGE_BYTES;
        const uint32_t bS = aS + TILE_BYTES;
#pragma unroll
        for (int i = 0; i < 8; i++) {
            const int c     = tid + 128 * i;      // 1024 chunks per tile
            const int row   = c >> 3;
            const int chunk = c & 7;
            cp16(swz(aS, row, chunk), Ab + (long)(m0 + row) * K + k0 + chunk * 8);
            cp16(swz(bS, row, chunk), Bb + (long)(n0 + row) * K + k0 + chunk * 8);
        }
    };

    float acc[4][8][4];
#pragma unroll
    for (int mt = 0; mt < 4; mt++)
#pragma unroll
        for (int nt = 0; nt < 8; nt++)
#pragma unroll
            for (int i = 0; i < 4; i++) acc[mt][nt][i] = 0.0f;

    const int KT = K / BK;
    load_tiles(0, 0);      cp_commit();
    if (KT > 1) { load_tiles(1, BK); cp_commit(); }

    uint32_t afr[2][4][4], bfr[2][4][4];

    for (int t = 0; t < KT; t++) {
        if (t + 2 < KT) asm volatile("cp.async.wait_group 1;");
        else            asm volatile("cp.async.wait_group 0;");
        __syncthreads();

        const int stage = t % STAGES;
        const uint32_t aS = smBase + (uint32_t)stage * STAGE_BYTES;
        const uint32_t bS = aS + TILE_BYTES;

        // critical-path fragments first...
#pragma unroll
        for (int mt = 0; mt < 4; mt++)
            ldsm4(afr[0][mt], swz(aS, wm + mt * 16 + aRow, aSub));
#pragma unroll
        for (int ng = 0; ng < 4; ng++)
            ldsm4(bfr[0][ng], swz(bS, wn + ng * 16 + bRow, bSub));

        // ...then issue the next-stage async loads (off critical path)
        if (t + 2 < KT) { load_tiles((t + 2) % STAGES, (t + 2) * BK); cp_commit(); }

#pragma unroll
        for (int ks = 0; ks < BK / 16; ks++) {
            const int cur = ks & 1;
            const int nxt = cur ^ 1;
            if (ks < BK / 16 - 1) {
                const int ch = (ks + 1) * 2;
#pragma unroll
                for (int mt = 0; mt < 4; mt++)
                    ldsm4(afr[nxt][mt], swz(aS, wm + mt * 16 + aRow, ch + aSub));
#pragma unroll
                for (int ng = 0; ng < 4; ng++)
                    ldsm4(bfr[nxt][ng], swz(bS, wn + ng * 16 + bRow, ch + bSub));
            }
#pragma unroll
            for (int mt = 0; mt < 4; mt++)
#pragma unroll
                for (int nt = 0; nt < 8; nt++)
                    mma_f16(acc[mt][nt], afr[cur][mt], &bfr[cur][nt >> 1][(nt & 1) * 2]);
        }
    }

    // epilogue
#pragma unroll
    for (int mt = 0; mt < 4; mt++) {
        const long row0 = m0 + wm + mt * 16 + r;
#pragma unroll
        for (int nt = 0; nt < 8; nt++) {
            const int colb = n0 + wn + nt * 8 + 2 * cc;
            float x0 = acc[mt][nt][0] * alpha;
            float x1 = acc[mt][nt][1] * alpha;
            float x2 = acc[mt][nt][2] * alpha;
            float x3 = acc[mt][nt][3] * alpha;
            if (HAS_BIAS) {
                const float b0 = biasb[colb], b1 = biasb[colb + 1];
                x0 += b0; x1 += b1; x2 += b0; x3 += b1;
            }
            if (OUT_HALF) {
                __half* Cb = (__half*)Cvb + (PROJ3 ? 0 : (long)z * sCz);
                *(__half2*)(Cb + row0 * N + colb)       = __floats2half2_rn(x0, x1);
                *(__half2*)(Cb + (row0 + 8) * N + colb) = __floats2half2_rn(x2, x3);
            } else {
                float* Cb = (float*)Cvb + (PROJ3 ? 0 : (long)z * sCz);
                *(float2*)(Cb + row0 * N + colb)       = make_float2(x0, x1);
                *(float2*)(Cb + (row0 + 8) * N + colb) = make_float2(x2, x3);
            }
        }
    }
}

// ---------------------------------------------------------------------------
// Batched fp32 -> fp16(rn): z selects which of 3 arrays
// ---------------------------------------------------------------------------
__global__ __launch_bounds__(256)
void f2h3_kernel(const float* __restrict__ a0, const float* __restrict__ a1,
                 const float* __restrict__ a2, __half* __restrict__ o0,
                 __half* __restrict__ o1, __half* __restrict__ o2, long n4)
{
    const float* in = (blockIdx.z == 0) ? a0 : (blockIdx.z == 1) ? a1 : a2;
    __half* out     = (blockIdx.z == 0) ? o0 : (blockIdx.z == 1) ? o1 : o2;
    long i = (long)blockIdx.x * blockDim.x + threadIdx.x;
    const long stride = (long)gridDim.x * blockDim.x;
    for (; i < n4; i += stride) {
        float4 v = ((const float4*)in)[i];
        __half2* o = (__half2*)(out + i * 4);
        o[0] = __floats2half2_rn(v.x, v.y);
        o[1] = __floats2half2_rn(v.z, v.w);
    }
}

// ---------------------------------------------------------------------------
// Batched transpose + convert: W f32 [K][N] -> half [N][K] (z selects weight)
// ---------------------------------------------------------------------------
__global__ __launch_bounds__(256)
void wtrans3_kernel(const float* __restrict__ a0, const float* __restrict__ a1,
                    const float* __restrict__ a2, __half* __restrict__ o0,
                    __half* __restrict__ o1, __half* __restrict__ o2)
{
    const float* in = (blockIdx.z == 0) ? a0 : (blockIdx.z == 1) ? a1 : a2;
    __half* out     = (blockIdx.z == 0) ? o0 : (blockIdx.z == 1) ? o1 : o2;
    __shared__ float t[32][33];
    const int bx = blockIdx.x * 32;   // n
    const int by = blockIdx.y * 32;   // k
    const int tx = threadIdx.x, ty = threadIdx.y;
#pragma unroll
    for (int i = ty; i < 32; i += 8)
        t[i][tx] = in[(long)(by + i) * DD + bx + tx];
    __syncthreads();
#pragma unroll
    for (int i = ty; i < 32; i += 8)
        out[(long)(bx + i) * DD + by + tx] = __float2half_rn(t[tx][i]);
}

// ---------------------------------------------------------------------------
// Half transpose (batched): in [rows][cols] -> out [cols][rows]
// ---------------------------------------------------------------------------
__global__ __launch_bounds__(256)
void htrans_kernel(const __half* __restrict__ in, __half* __restrict__ out,
                   int rows, int cols)
{
    __shared__ __half t[32][34];
    const int bx = blockIdx.x * 32;   // col
    const int by = blockIdx.y * 32;   // row
    const int tx = threadIdx.x, ty = threadIdx.y;
    const __half* ib = in  + (long)blockIdx.z * rows * cols;
    __half*       ob = out + (long)blockIdx.z * rows * cols;
#pragma unroll
    for (int i = ty; i < 32; i += 8)
        t[i][tx] = ib[(long)(by + i) * cols + bx + tx];
    __syncthreads();
#pragma unroll
    for (int i = ty; i < 32; i += 8)
        ob[(long)(bx + i) * rows + by + tx] = t[tx][i];
}

// ---------------------------------------------------------------------------
// Row softmax over 2048 fp32 cols -> fp16 probabilities
// ---------------------------------------------------------------------------
__global__ __launch_bounds__(256)
void softmax2048_h(const float* __restrict__ S, __half* __restrict__ P)
{
    const float* row = S + (long)blockIdx.x * SS;
    __half*      po  = P + (long)blockIdx.x * SS;
    const int t = threadIdx.x;

    float v[8];
    float mx = -1e30f;
#pragma unroll
    for (int i = 0; i < 8; i++) {
        v[i] = row[t + i * 256];
        mx = fmaxf(mx, v[i]);
    }
#pragma unroll
    for (int o = 16; o > 0; o >>= 1)
        mx = fmaxf(mx, __shfl_xor_sync(0xFFFFFFFFu, mx, o));

    __shared__ float red[8];
    if ((t & 31) == 0) red[t >> 5] = mx;
    __syncthreads();
    float bmax = red[0];
#pragma unroll
    for (int i = 1; i < 8; i++) bmax = fmaxf(bmax, red[i]);
    __syncthreads();

    float sum = 0.0f;
#pragma unroll
    for (int i = 0; i < 8; i++) {
        v[i] = __expf(v[i] - bmax);
        sum += v[i];
    }
#pragma unroll
    for (int o = 16; o > 0; o >>= 1)
        sum += __shfl_xor_sync(0xFFFFFFFFu, sum, o);
    if ((t & 31) == 0) red[t >> 5] = sum;
    __syncthreads();
    float tot = 0.0f;
#pragma unroll
    for (int i = 0; i < 8; i++) tot += red[i];

    const float inv = __frcp_rn(tot);
#pragma unroll
    for (int i = 0; i < 8; i++)
        po[t + i * 256] = __float2half_rn(v[i] * inv);
}

// ---------------------------------------------------------------------------
extern "C" void kernel_launch(void* const* d_in, const int* in_sizes, int n_in,
                              void* d_out, int out_size)
{
    const float* q  = (const float*)d_in[0];
    const float* k  = (const float*)d_in[1];
    const float* v  = (const float*)d_in[2];
    const float* Wq = (const float*)d_in[3];
    const float* bq = (const float*)d_in[4];
    const float* Wk = (const float*)d_in[5];
    const float* bk = (const float*)d_in[6];
    const float* Wv = (const float*)d_in[7];
    const float* bv = (const float*)d_in[8];
    float* out = (float*)d_out;

    __half *qh, *kh, *vh, *WqT, *WkT, *WvT, *Qp, *Kp, *Vp, *VpT, *Ph;
    float *Sc;
    cudaGetSymbolAddress((void**)&qh,  g_qh);
    cudaGetSymbolAddress((void**)&kh,  g_kh);
    cudaGetSymbolAddress((void**)&vh,  g_vh);
    cudaGetSymbolAddress((void**)&WqT, g_WqT);
    cudaGetSymbolAddress((void**)&WkT, g_WkT);
    cudaGetSymbolAddress((void**)&WvT, g_WvT);
    cudaGetSymbolAddress((void**)&Qp,  g_Qp);
    cudaGetSymbolAddress((void**)&Kp,  g_Kp);
    cudaGetSymbolAddress((void**)&Vp,  g_Vp);
    cudaGetSymbolAddress((void**)&VpT, g_VpT);
    cudaGetSymbolAddress((void**)&Sc,  g_Sc);
    cudaGetSymbolAddress((void**)&Ph,  g_Ph);

    cudaFuncSetAttribute(hgemm_tn<true,  true,  true >, cudaFuncAttributeMaxDynamicSharedMemorySize, GEMM_SMEM);
    cudaFuncSetAttribute(hgemm_tn<false, false, false>, cudaFuncAttributeMaxDynamicSharedMemorySize, GEMM_SMEM);

    const long nQKV = (long)BB * SS * DD;

    // 1: convert q/k/v to fp16 (one launch, grid.z = 3)
    {
        dim3 g(1024, 1, 3);
        f2h3_kernel<<<g, 256>>>(q, k, v, qh, kh, vh, nQKV / 4);
    }
    // 2: transpose+convert weights (one launch, grid.z = 3)
    {
        dim3 g(32, 32, 3), b(32, 8);
        wtrans3_kernel<<<g, b>>>(Wq, Wk, Wv, WqT, WkT, WvT);
    }

    const dim3 blk(128);

    // 3: Projections, batched into ONE launch (z selects q/k/v triple)
    {
        dim3 g(DD / 128, (BB * SS) / 128, 3);
        hgemm_tn<true, true, true><<<g, blk, GEMM_SMEM>>>(
            qh, WqT, bq, Qp, DD, DD, 1.0f, 0, 0, 0,
            kh, WkT, bk, Kp,
            vh, WvT, bv, Vp);
    }

    // 4: Scores (TN, f32 out): per batch M=N=2048, K=1024, alpha=1/32
    {
        dim3 g(SS / 128, SS / 128, BB);
        hgemm_tn<false, false, false><<<g, blk, GEMM_SMEM>>>(
            Qp, Kp, nullptr, Sc, SS, DD, 0.03125f,
            (long)SS * DD, (long)SS * DD, (long)SS * SS,
            nullptr, nullptr, nullptr, nullptr,
            nullptr, nullptr, nullptr, nullptr);
    }

    // 5: Softmax (f32 -> f16 probs)
    softmax2048_h<<<BB * SS, 256>>>(Sc, Ph);

    // 6: transpose Vp per batch: [S][D] -> [D][S]
    {
        dim3 g(DD / 32, SS / 32, BB), b(32, 8);
        htrans_kernel<<<g, b>>>(Vp, VpT, SS, DD);
    }

    // 7: PV (TN, f32 out): A=Ph [S,S], B=VpT [D][S]; M=2048, N=1024, K=2048
    {
        dim3 g(DD / 128, SS / 128, BB);
        hgemm_tn<false, false, false><<<g, blk, GEMM_SMEM>>>(
            Ph, VpT, nullptr, out, DD, SS, 1.0f,
            (long)SS * SS, (long)SS * DD, (long)SS * DD,
            nullptr, nullptr, nullptr, nullptr,
            nullptr, nullptr, nullptr, nullptr);
    }
}

// round 12
// speedup vs baseline: 1.2962x; 1.0389x over previous
#include <cuda_runtime.h>
#include <cuda_fp16.h>
#include <cstdint>
#include <math.h>

#define BB 4
#define SS 2048
#define DD 1024

// Scratch (__device__ globals — allocation-free rule). 16B-aligned for cp.async.
__device__ __align__(256) __half g_qh [(size_t)BB * SS * DD];
__device__ __align__(256) __half g_kh [(size_t)BB * SS * DD];
__device__ __align__(256) __half g_vh [(size_t)BB * SS * DD];
__device__ __align__(256) __half g_WqT[(size_t)DD * DD];
__device__ __align__(256) __half g_WkT[(size_t)DD * DD];
__device__ __align__(256) __half g_WvT[(size_t)DD * DD];
__device__ __align__(256) __half g_Qp [(size_t)BB * SS * DD];
__device__ __align__(256) __half g_Kp [(size_t)BB * SS * DD];
__device__ __align__(256) __half g_Vp [(size_t)BB * SS * DD];
__device__ __align__(256) float  g_Sc [(size_t)BB * SS * SS];
__device__ __align__(256) __half g_Ph [(size_t)BB * SS * SS];

// ---------------------------------------------------------------------------
// PTX helpers
// ---------------------------------------------------------------------------
__device__ __forceinline__ void cp16(uint32_t dst, const void* src) {
    asm volatile("cp.async.cg.shared.global [%0], [%1], 16;" :: "r"(dst), "l"(src));
}
__device__ __forceinline__ void cp_commit() {
    asm volatile("cp.async.commit_group;");
}
__device__ __forceinline__ void ldsm4(uint32_t* r, uint32_t addr) {
    asm volatile("ldmatrix.sync.aligned.m8n8.x4.shared.b16 {%0,%1,%2,%3}, [%4];"
        : "=r"(r[0]), "=r"(r[1]), "=r"(r[2]), "=r"(r[3]) : "r"(addr));
}
__device__ __forceinline__ void ldsm4t(uint32_t* r, uint32_t addr) {
    asm volatile("ldmatrix.sync.aligned.m8n8.x4.trans.shared.b16 {%0,%1,%2,%3}, [%4];"
        : "=r"(r[0]), "=r"(r[1]), "=r"(r[2]), "=r"(r[3]) : "r"(addr));
}
__device__ __forceinline__ void mma_f16(float* c, const uint32_t* a, const uint32_t* b) {
    asm volatile(
        "mma.sync.aligned.m16n8k16.row.col.f32.f16.f16.f32 "
        "{%0,%1,%2,%3}, {%4,%5,%6,%7}, {%8,%9}, {%0,%1,%2,%3};"
        : "+f"(c[0]), "+f"(c[1]), "+f"(c[2]), "+f"(c[3])
        : "r"(a[0]), "r"(a[1]), "r"(a[2]), "r"(a[3]), "r"(b[0]), "r"(b[1]));
}

// SW128 swizzle for 128B logical rows (TN tiles: row = 64 halves, 8x16B chunks)
__device__ __forceinline__ uint32_t swz(uint32_t base, int row, int chunk) {
    return base + (uint32_t)(row * 128) + (uint32_t)((chunk ^ (row & 7)) << 4);
}
// Swizzle for 256B logical rows (NN B tile: 64 k-rows x 128 n-cols halves).
// ch16 in [0,16); XOR by (row&7)*2 keeps ldsm.trans row-reads conflict-free.
__device__ __forceinline__ uint32_t swzNN(uint32_t base, int row, int ch16) {
    return base + (uint32_t)(row * 256) + (uint32_t)((ch16 ^ ((row & 7) << 1)) << 4);
}

// ---------------------------------------------------------------------------
// FP16 tensor-core GEMM.
//   TN (BNN=false): C[m,n] = alpha * sum_k A[m,k]*B[n,k] (+bias), B [N,K] row-major.
//   NN (BNN=true) : C[m,n] = alpha * sum_k A[m,k]*B[k,n],          B [K,N] row-major.
//   128 threads, CTA tile 128x128x64, 4 warps 64x64, 3-stage cp.async,
//   SW128 swizzle, fragment double-buffering.
//   PROJ3: blockIdx.z selects one of 3 (A,B,bias,C) sets; else z = batch.
// ---------------------------------------------------------------------------
#define STAGES 3
#define BK 64
#define TILE_BYTES 16384                    // A: 128x128B;  B(TN): 128x128B; B(NN): 64x256B
#define STAGE_BYTES (2 * TILE_BYTES)        // 32768
#define GEMM_SMEM (STAGES * STAGE_BYTES)    // 98304

template <bool PROJ3, bool BNN, bool HAS_BIAS, bool OUT_HALF>
__global__ __launch_bounds__(128, 2)
void hgemm(const __half* __restrict__ A, const __half* __restrict__ B,
           const float* __restrict__ bias, void* __restrict__ Cv,
           int N, int K, int ldB, float alpha, long sAz, long sBz, long sCz,
           const __half* __restrict__ A1, const __half* __restrict__ B1,
           const float* __restrict__ bias1, void* __restrict__ Cv1,
           const __half* __restrict__ A2, const __half* __restrict__ B2,
           const float* __restrict__ bias2, void* __restrict__ Cv2)
{
    extern __shared__ __align__(1024) char smraw[];
    const int tid  = threadIdx.x;
    const int lane = tid & 31;
    const int warp = tid >> 5;
    const int m0 = blockIdx.y * 128;
    const int n0 = blockIdx.x * 128;
    const int z  = blockIdx.z;

    const __half* Ab;
    const __half* Bb;
    const float*  biasb;
    void*         Cvb;
    if (PROJ3) {
        Ab    = (z == 0) ? A    : (z == 1) ? A1    : A2;
        Bb    = (z == 0) ? B    : (z == 1) ? B1    : B2;
        biasb = (z == 0) ? bias : (z == 1) ? bias1 : bias2;
        Cvb   = (z == 0) ? Cv   : (z == 1) ? Cv1   : Cv2;
    } else {
        Ab    = A + (long)z * sAz;
        Bb    = B + (long)z * sBz;
        biasb = bias;
        Cvb   = Cv;
    }

    const int wm = (warp >> 1) * 64;
    const int wn = (warp & 1) * 64;
    const int r  = lane >> 2;
    const int cc = lane & 3;

    const uint32_t smBase = (uint32_t)__cvta_generic_to_shared(smraw);

    // ldmatrix lane mapping
    const int aRow = lane & 15;
    const int aSub = lane >> 4;
    const int bRow = ((lane >> 4) << 3) + (lane & 7);     // TN
    const int bSub = (lane >> 3) & 1;                     // TN
    const int kLanePart = (((lane >> 3) & 1) << 3) + (lane & 7);  // NN: k row within 16
    const int nLanePart = (lane >> 4);                            // NN: n-chunk select

    auto load_tiles = [&](int stage, int k0) {
        const uint32_t aS = smBase + (uint32_t)stage * STAGE_BYTES;
        const uint32_t bS = aS + TILE_BYTES;
#pragma unroll
        for (int i = 0; i < 8; i++) {
            const int c = tid + 128 * i;                  // 1024 x 16B chunks per tile
            {   // A tile: 128 m-rows x 128 B
                const int row   = c >> 3;
                const int chunk = c & 7;
                cp16(swz(aS, row, chunk), Ab + (long)(m0 + row) * K + k0 + chunk * 8);
            }
            if (BNN) {   // B tile: 64 k-rows x 256 B
                const int row  = c >> 4;
                const int ch16 = c & 15;
                cp16(swzNN(bS, row, ch16), Bb + (long)(k0 + row) * ldB + n0 + ch16 * 8);
            } else {     // B tile: 128 n-rows x 128 B
                const int row   = c >> 3;
                const int chunk = c & 7;
                cp16(swz(bS, row, chunk), Bb + (long)(n0 + row) * ldB + k0 + chunk * 8);
            }
        }
    };

    float acc[4][8][4];
#pragma unroll
    for (int mt = 0; mt < 4; mt++)
#pragma unroll
        for (int nt = 0; nt < 8; nt++)
#pragma unroll
            for (int i = 0; i < 4; i++) acc[mt][nt][i] = 0.0f;

    const int KT = K / BK;
    load_tiles(0, 0);      cp_commit();
    if (KT > 1) { load_tiles(1, BK); cp_commit(); }

    uint32_t afr[2][4][4], bfr[2][4][4];

    auto loadA = [&](uint32_t f[4][4], uint32_t aS, int ks) {
#pragma unroll
        for (int mt = 0; mt < 4; mt++)
            ldsm4(f[mt], swz(aS, wm + mt * 16 + aRow, ks * 2 + aSub));
    };
    auto loadB = [&](uint32_t f[4][4], uint32_t bS, int ks) {
        if (BNN) {
            const int kl = ks * 16 + kLanePart;
#pragma unroll
            for (int ng = 0; ng < 4; ng++) {
                const int nch = (wn >> 3) + ng * 2 + nLanePart;
                ldsm4t(f[ng], swzNN(bS, kl, nch));
            }
        } else {
#pragma unroll
            for (int ng = 0; ng < 4; ng++)
                ldsm4(f[ng], swz(bS, wn + ng * 16 + bRow, ks * 2 + bSub));
        }
    };

    for (int t = 0; t < KT; t++) {
        if (t + 2 < KT) asm volatile("cp.async.wait_group 1;");
        else            asm volatile("cp.async.wait_group 0;");
        __syncthreads();

        const int stage = t % STAGES;
        const uint32_t aS = smBase + (uint32_t)stage * STAGE_BYTES;
        const uint32_t bS = aS + TILE_BYTES;

        // critical-path fragments first...
        loadA(afr[0], aS, 0);
        loadB(bfr[0], bS, 0);

        // ...then next-stage async loads (off critical path)
        if (t + 2 < KT) { load_tiles((t + 2) % STAGES, (t + 2) * BK); cp_commit(); }

#pragma unroll
        for (int ks = 0; ks < BK / 16; ks++) {
            const int cur = ks & 1;
            const int nxt = cur ^ 1;
            if (ks < BK / 16 - 1) {
                loadA(afr[nxt], aS, ks + 1);
                loadB(bfr[nxt], bS, ks + 1);
            }
#pragma unroll
            for (int mt = 0; mt < 4; mt++)
#pragma unroll
                for (int nt = 0; nt < 8; nt++)
                    mma_f16(acc[mt][nt], afr[cur][mt], &bfr[cur][nt >> 1][(nt & 1) * 2]);
        }
    }

    // epilogue
#pragma unroll
    for (int mt = 0; mt < 4; mt++) {
        const long row0 = m0 + wm + mt * 16 + r;
#pragma unroll
        for (int nt = 0; nt < 8; nt++) {
            const int colb = n0 + wn + nt * 8 + 2 * cc;
            float x0 = acc[mt][nt][0] * alpha;
            float x1 = acc[mt][nt][1] * alpha;
            float x2 = acc[mt][nt][2] * alpha;
            float x3 = acc[mt][nt][3] * alpha;
            if (HAS_BIAS) {
                const float b0 = biasb[colb], b1 = biasb[colb + 1];
                x0 += b0; x1 += b1; x2 += b0; x3 += b1;
            }
            if (OUT_HALF) {
                __half* Cb = (__half*)Cvb + (PROJ3 ? 0 : (long)z * sCz);
                *(__half2*)(Cb + row0 * N + colb)       = __floats2half2_rn(x0, x1);
                *(__half2*)(Cb + (row0 + 8) * N + colb) = __floats2half2_rn(x2, x3);
            } else {
                float* Cb = (float*)Cvb + (PROJ3 ? 0 : (long)z * sCz);
                *(float2*)(Cb + row0 * N + colb)       = make_float2(x0, x1);
                *(float2*)(Cb + (row0 + 8) * N + colb) = make_float2(x2, x3);
            }
        }
    }
}

// ---------------------------------------------------------------------------
// Batched fp32 -> fp16(rn): z selects which of 3 arrays
// ---------------------------------------------------------------------------
__global__ __launch_bounds__(256)
void f2h3_kernel(const float* __restrict__ a0, const float* __restrict__ a1,
                 const float* __restrict__ a2, __half* __restrict__ o0,
                 __half* __restrict__ o1, __half* __restrict__ o2, long n4)
{
    const float* in = (blockIdx.z == 0) ? a0 : (blockIdx.z == 1) ? a1 : a2;
    __half* out     = (blockIdx.z == 0) ? o0 : (blockIdx.z == 1) ? o1 : o2;
    long i = (long)blockIdx.x * blockDim.x + threadIdx.x;
    const long stride = (long)gridDim.x * blockDim.x;
    for (; i < n4; i += stride) {
        float4 v = ((const float4*)in)[i];
        __half2* o = (__half2*)(out + i * 4);
        o[0] = __floats2half2_rn(v.x, v.y);
        o[1] = __floats2half2_rn(v.z, v.w);
    }
}

// ---------------------------------------------------------------------------
// Batched transpose + convert: W f32 [K][N] -> half [N][K] (z selects weight)
// ---------------------------------------------------------------------------
__global__ __launch_bounds__(256)
void wtrans3_kernel(const float* __restrict__ a0, const float* __restrict__ a1,
                    const float* __restrict__ a2, __half* __restrict__ o0,
                    __half* __restrict__ o1, __half* __restrict__ o2)
{
    const float* in = (blockIdx.z == 0) ? a0 : (blockIdx.z == 1) ? a1 : a2;
    __half* out     = (blockIdx.z == 0) ? o0 : (blockIdx.z == 1) ? o1 : o2;
    __shared__ float t[32][33];
    const int bx = blockIdx.x * 32;   // n
    const int by = blockIdx.y * 32;   // k
    const int tx = threadIdx.x, ty = threadIdx.y;
#pragma unroll
    for (int i = ty; i < 32; i += 8)
        t[i][tx] = in[(long)(by + i) * DD + bx + tx];
    __syncthreads();
#pragma unroll
    for (int i = ty; i < 32; i += 8)
        out[(long)(bx + i) * DD + by + tx] = __float2half_rn(t[tx][i]);
}

// ---------------------------------------------------------------------------
// Row softmax over 2048 fp32 cols -> fp16 probabilities (vectorized)
// ---------------------------------------------------------------------------
__global__ __launch_bounds__(256)
void softmax2048_h(const float* __restrict__ S, __half* __restrict__ P)
{
    const float4* row = (const float4*)(S + (long)blockIdx.x * SS);
    uint2*        po  = (uint2*)(P + (long)blockIdx.x * SS);
    const int t = threadIdx.x;

    float4 v4[2];
    float v[8];
    float mx = -1e30f;
#pragma unroll
    for (int i = 0; i < 2; i++) {
        v4[i] = row[t + i * 256];
        v[i*4+0] = v4[i].x; v[i*4+1] = v4[i].y; v[i*4+2] = v4[i].z; v[i*4+3] = v4[i].w;
    }
#pragma unroll
    for (int i = 0; i < 8; i++) mx = fmaxf(mx, v[i]);
#pragma unroll
    for (int o = 16; o > 0; o >>= 1)
        mx = fmaxf(mx, __shfl_xor_sync(0xFFFFFFFFu, mx, o));

    __shared__ float red[8];
    if ((t & 31) == 0) red[t >> 5] = mx;
    __syncthreads();
    float bmax = red[0];
#pragma unroll
    for (int i = 1; i < 8; i++) bmax = fmaxf(bmax, red[i]);
    __syncthreads();

    float sum = 0.0f;
#pragma unroll
    for (int i = 0; i < 8; i++) {
        v[i] = __expf(v[i] - bmax);
        sum += v[i];
    }
#pragma unroll
    for (int o = 16; o > 0; o >>= 1)
        sum += __shfl_xor_sync(0xFFFFFFFFu, sum, o);
    if ((t & 31) == 0) red[t >> 5] = sum;
    __syncthreads();
    float tot = 0.0f;
#pragma unroll
    for (int i = 0; i < 8; i++) tot += red[i];

    const float inv = __frcp_rn(tot);
#pragma unroll
    for (int i = 0; i < 2; i++) {
        __half2 h0 = __floats2half2_rn(v[i*4+0] * inv, v[i*4+1] * inv);
        __half2 h1 = __floats2half2_rn(v[i*4+2] * inv, v[i*4+3] * inv);
        uint2 u;
        u.x = *(uint32_t*)&h0;
        u.y = *(uint32_t*)&h1;
        po[t + i * 256] = u;
    }
}

// ---------------------------------------------------------------------------
extern "C" void kernel_launch(void* const* d_in, const int* in_sizes, int n_in,
                              void* d_out, int out_size)
{
    const float* q  = (const float*)d_in[0];
    const float* k  = (const float*)d_in[1];
    const float* v  = (const float*)d_in[2];
    const float* Wq = (const float*)d_in[3];
    const float* bq = (const float*)d_in[4];
    const float* Wk = (const float*)d_in[5];
    const float* bk = (const float*)d_in[6];
    const float* Wv = (const float*)d_in[7];
    const float* bv = (const float*)d_in[8];
    float* out = (float*)d_out;

    __half *qh, *kh, *vh, *WqT, *WkT, *WvT, *Qp, *Kp, *Vp, *Ph;
    float *Sc;
    cudaGetSymbolAddress((void**)&qh,  g_qh);
    cudaGetSymbolAddress((void**)&kh,  g_kh);
    cudaGetSymbolAddress((void**)&vh,  g_vh);
    cudaGetSymbolAddress((void**)&WqT, g_WqT);
    cudaGetSymbolAddress((void**)&WkT, g_WkT);
    cudaGetSymbolAddress((void**)&WvT, g_WvT);
    cudaGetSymbolAddress((void**)&Qp,  g_Qp);
    cudaGetSymbolAddress((void**)&Kp,  g_Kp);
    cudaGetSymbolAddress((void**)&Vp,  g_Vp);
    cudaGetSymbolAddress((void**)&Sc,  g_Sc);
    cudaGetSymbolAddress((void**)&Ph,  g_Ph);

    cudaFuncSetAttribute(hgemm<true,  false, true,  true >, cudaFuncAttributeMaxDynamicSharedMemorySize, GEMM_SMEM);
    cudaFuncSetAttribute(hgemm<false, false, false, false>, cudaFuncAttributeMaxDynamicSharedMemorySize, GEMM_SMEM);
    cudaFuncSetAttribute(hgemm<false, true,  false, false>, cudaFuncAttributeMaxDynamicSharedMemorySize, GEMM_SMEM);

    const long nQKV = (long)BB * SS * DD;

    // 1: convert q/k/v to fp16 (one launch, grid.z = 3)
    {
        dim3 g(1024, 1, 3);
        f2h3_kernel<<<g, 256>>>(q, k, v, qh, kh, vh, nQKV / 4);
    }
    // 2: transpose+convert weights (one launch, grid.z = 3)
    {
        dim3 g(32, 32, 3), b(32, 8);
        wtrans3_kernel<<<g, b>>>(Wq, Wk, Wv, WqT, WkT, WvT);
    }

    const dim3 blk(128);

    // 3: Projections, batched into ONE launch (z selects q/k/v triple)
    {
        dim3 g(DD / 128, (BB * SS) / 128, 3);
        hgemm<true, false, true, true><<<g, blk, GEMM_SMEM>>>(
            qh, WqT, bq, Qp, DD, DD, DD, 1.0f, 0, 0, 0,
            kh, WkT, bk, Kp,
            vh, WvT, bv, Vp);
    }

    // 4: Scores (TN, f32 out): per batch M=N=2048, K=1024, alpha=1/32
    {
        dim3 g(SS / 128, SS / 128, BB);
        hgemm<false, false, false, false><<<g, blk, GEMM_SMEM>>>(
            Qp, Kp, nullptr, Sc, SS, DD, DD, 0.03125f,
            (long)SS * DD, (long)SS * DD, (long)SS * SS,
            nullptr, nullptr, nullptr, nullptr,
            nullptr, nullptr, nullptr, nullptr);
    }

    // 5: Softmax (f32 -> f16 probs)
    softmax2048_h<<<BB * SS, 256>>>(Sc, Ph);

    // 6: PV (NN, f32 out): A=Ph [S,S], B=Vp [S,D] k-major; M=2048, N=1024, K=2048
    {
        dim3 g(DD / 128, SS / 128, BB);
        hgemm<false, true, false, false><<<g, blk, GEMM_SMEM>>>(
            Ph, Vp, nullptr, out, DD, SS, DD, 1.0f,
            (long)SS * SS, (long)SS * DD, (long)SS * DD,
            nullptr, nullptr, nullptr, nullptr,
            nullptr, nullptr, nullptr, nullptr);
    }
}